// round 9
// baseline (speedup 1.0000x reference)
#include <cuda_runtime.h>
#include <cuda_bf16.h>

// DMN_Encoder: 3-hop memory network, B=128, N=2048, D=128.
// Four-launch pipeline, heavy phases at grid B*8 (=1024 CTAs):
//  K1: per 256-row slice -> compaction, stream active fp32 rows ONCE,
//      compute hop-invariant s=v·w_f, write segment-compacted bf16 copy,
//      fuse hop-0 accumulation (cb0 needs only e1). Emit per-slice partials.
//  hop<1>, hop<2>: grid 1024; each slice-CTA redundantly reconstructs u_h
//      from prior partials (tiny GEMV chain), sweeps its slice's s values,
//      streams its contiguous bf16 segment, emits per-slice partials.
//  hop<3>: grid 128; reconstructs u3, writes output.
// Plain LDG/STG only; hop is a compile-time template parameter.

#define B_ 128
#define N_ 2048
#define D_ 128
#define SLICES 8
#define SROWS (N_ / SLICES)          // 256

__device__ uint2  g_vbf[(size_t)B_ * N_ * (D_ / 4)];     // 67MB bf16 scratch (segment compact)
__device__ float  g_s[(size_t)B_ * N_];                  // hop-invariant s (segment compact)
__device__ float  g_part[3 * (size_t)B_ * SLICES * 132]; // per-hop per-slice partials
__device__ int    g_cnt[(size_t)B_ * SLICES];

// ============================ K1 ============================
__global__ __launch_bounds__(256, 4)
void dmn_k1(const float* __restrict__ e1,
            const float* __restrict__ value,
            const float* __restrict__ mask,
            const float* __restrict__ attw,
            const float* __restrict__ attb)
{
    const int blk  = blockIdx.x;
    const int b    = blk >> 3;
    const int sl   = blk & 7;
    const int tid  = threadIdx.x;
    const int lane = tid & 31;
    const int warp = tid >> 5;           // 0..7

    __shared__ unsigned short tmp_s[SROWS];
    __shared__ unsigned short dense_s[SROWS];
    __shared__ int cntw_s[8], offw_s[8], tot_s;
    __shared__ __align__(16) float acc_s[8][D_];
    __shared__ float lpart_s[8];

    const float4* attw4 = reinterpret_cast<const float4*>(attw);
    const float4 wf4 = attw4[lane];
    const float4 wu4 = attw4[32 + lane];

    // ---- ballot compaction of this slice's active rows ----
    {
        const float m = mask[(size_t)b * N_ + sl * SROWS + warp * 32 + lane];
        const unsigned bal = __ballot_sync(0xffffffffu, m != 0.f);
        if (m != 0.f)
            tmp_s[warp * 32 + __popc(bal & ((1u << lane) - 1u))]
                = (unsigned short)(warp * 32 + lane);
        if (lane == 0) cntw_s[warp] = __popc(bal);
    }
    __syncthreads();
    if (tid == 0) {
        int o = 0;
        #pragma unroll
        for (int i = 0; i < 8; i++) { offw_s[i] = o; o += cntw_s[i]; }
        tot_s = o;
    }
    __syncthreads();
    for (int j = lane; j < cntw_s[warp]; j += 32)
        dense_s[offw_s[warp] + j] = tmp_s[warp * 32 + j];

    // ---- cb0 = e1·w_u + b0 ----
    const float4 e4 = reinterpret_cast<const float4*>(e1 + (size_t)b * D_)[lane];
    float cp = e4.x*wu4.x + e4.y*wu4.y + e4.z*wu4.z + e4.w*wu4.w;
    #pragma unroll
    for (int o = 16; o; o >>= 1) cp += __shfl_xor_sync(0xffffffffu, cp, o);
    const float cb    = cp + attb[0];
    const float sigma = fmaxf(cb, 0.f);
    __syncthreads();

    const int cnt = tot_s;
    const int kb  = (cnt * warp) >> 3;
    const int ke  = (cnt * (warp + 1)) >> 3;

    const float* vb = value + (size_t)b * N_ * D_;
    float a0 = 0.f, a1 = 0.f, a2 = 0.f, a3 = 0.f, l = 0.f;

    #pragma unroll 4
    for (int k = kb; k < ke; k++) {
        const int n  = sl * SROWS + dense_s[k];
        const int kp = sl * SROWS + k;
        const float4 v4 = reinterpret_cast<const float4*>(vb + (size_t)n * D_)[lane];
        float s = v4.x*wf4.x + v4.y*wf4.y + v4.z*wf4.z + v4.w*wf4.w;
        #pragma unroll
        for (int o = 16; o; o >>= 1) s += __shfl_xor_sync(0xffffffffu, s, o);
        if (lane == 0) g_s[(size_t)b * N_ + kp] = s;
        __nv_bfloat162 p0 = __floats2bfloat162_rn(v4.x, v4.y);
        __nv_bfloat162 p1 = __floats2bfloat162_rn(v4.z, v4.w);
        uint2 pk;
        pk.x = *reinterpret_cast<unsigned int*>(&p0);
        pk.y = *reinterpret_cast<unsigned int*>(&p1);
        g_vbf[((size_t)b * N_ + kp) * 32 + lane] = pk;
        const float att = fmaxf(s + cb, 0.f);
        const float w   = __expf(fminf(att - sigma, 80.f));
        l += w;
        a0 = fmaf(w, v4.x, a0);
        a1 = fmaf(w, v4.y, a1);
        a2 = fmaf(w, v4.z, a2);
        a3 = fmaf(w, v4.w, a3);
    }

    reinterpret_cast<float4*>(&acc_s[warp][lane * 4])[0] = make_float4(a0, a1, a2, a3);
    if (lane == 0) lpart_s[warp] = l;
    __syncthreads();

    float* part = g_part + ((size_t)b * SLICES + sl) * 132;
    if (tid < D_) {
        float o = 0.f;
        #pragma unroll
        for (int w = 0; w < 8; w++) o += acc_s[w][tid];
        part[tid] = o;
    } else if (tid == D_) {
        float lt = 0.f;
        #pragma unroll
        for (int w = 0; w < 8; w++) lt += lpart_s[w];
        part[D_] = lt;
    } else if (tid == D_ + 1) {
        g_cnt[b * SLICES + sl] = cnt;
    }
}

// ============================ hop kernel ============================
template <int HOP>
__global__ __launch_bounds__(256, 4)
void dmn_hop(const float* __restrict__ e1,
             const float* __restrict__ linw,
             const float* __restrict__ linb,
             const float* __restrict__ attw,
             const float* __restrict__ attb,
             float* __restrict__ out)
{
    const int b    = (HOP == 3) ? blockIdx.x : (blockIdx.x >> 3);
    const int sl   = (HOP == 3) ? 0          : (blockIdx.x & 7);
    const int tid  = threadIdx.x;
    const int lane = tid & 31;
    const int warp = tid >> 5;           // 0..7

    __shared__ __align__(16) float u_s[D_];
    __shared__ __align__(16) float ub_s[D_];
    __shared__ __align__(16) float acc_s[8][D_];
    __shared__ float w_c[SROWS];
    __shared__ float lw_s[8];

    const float4* attw4 = reinterpret_cast<const float4*>(attw);
    const float4 wu4 = attw4[32 + lane];

    // ---- reconstruct u_HOP from partial chain (redundant per CTA) ----
    if (tid < D_) u_s[tid] = e1[(size_t)b * D_ + tid];
    __syncthreads();
    #pragma unroll 1
    for (int hh = 1; hh <= HOP; hh++) {
        const float4 u4 = reinterpret_cast<const float4*>(u_s)[lane];
        #pragma unroll
        for (int r = 0; r < 16; r++) {
            const int i = warp * 16 + r;
            const float4 w4 = reinterpret_cast<const float4*>(linw + (size_t)i * D_)[lane];
            float p = w4.x*u4.x + w4.y*u4.y + w4.z*u4.z + w4.w*u4.w;
            #pragma unroll
            for (int o = 16; o; o >>= 1) p += __shfl_xor_sync(0xffffffffu, p, o);
            if (lane == 0) ub_s[i] = fmaxf(p + linb[i], 0.f);
        }
        __syncthreads();
        if (tid < D_) {
            const float* part = g_part + ((size_t)(hh - 1) * B_ + b) * SLICES * 132;
            float oa = 0.f, lt = 1e-5f;
            #pragma unroll
            for (int s2 = 0; s2 < 8; s2++) {
                oa += part[s2 * 132 + tid];
                lt += part[s2 * 132 + D_];
            }
            u_s[tid] = ub_s[tid] + oa / lt;
        }
        __syncthreads();
    }

    if (HOP == 3) {
        if (tid < D_) out[(size_t)b * D_ + tid] = u_s[tid];
        return;
    }

    // ---- cb = u·w_u + b0 ----
    const float4 u4 = reinterpret_cast<const float4*>(u_s)[lane];
    float cp = u4.x*wu4.x + u4.y*wu4.y + u4.z*wu4.z + u4.w*wu4.w;
    #pragma unroll
    for (int o = 16; o; o >>= 1) cp += __shfl_xor_sync(0xffffffffu, cp, o);
    const float cb    = cp + attb[0];
    const float sigma = fmaxf(cb, 0.f);

    const int cnt = g_cnt[b * SLICES + sl];

    // ---- weight sweep over this slice's s (one thread per row) ----
    float lsum = 0.f;
    if (tid < cnt) {
        const float s   = g_s[(size_t)b * N_ + sl * SROWS + tid];
        const float att = fmaxf(s + cb, 0.f);
        const float w   = __expf(fminf(att - sigma, 80.f));
        w_c[tid] = w;
        lsum = w;
    }
    #pragma unroll
    for (int o = 16; o; o >>= 1) lsum += __shfl_xor_sync(0xffffffffu, lsum, o);
    if (lane == 0) lw_s[warp] = lsum;
    __syncthreads();

    // ---- contiguous bf16 stream over this slice's segment ----
    const int kb = (cnt * warp) >> 3;
    const int ke = (cnt * (warp + 1)) >> 3;
    const uint2* vseg = g_vbf + ((size_t)b * N_ + sl * SROWS) * 32;
    float a0 = 0.f, a1 = 0.f, a2 = 0.f, a3 = 0.f;
    #pragma unroll 8
    for (int k = kb; k < ke; k++) {
        const uint2 pk = vseg[(size_t)k * 32 + lane];
        const float w  = w_c[k];
        const float2 f0 = __bfloat1622float2(*reinterpret_cast<const __nv_bfloat162*>(&pk.x));
        const float2 f1 = __bfloat1622float2(*reinterpret_cast<const __nv_bfloat162*>(&pk.y));
        a0 = fmaf(w, f0.x, a0);
        a1 = fmaf(w, f0.y, a1);
        a2 = fmaf(w, f1.x, a2);
        a3 = fmaf(w, f1.y, a3);
    }

    reinterpret_cast<float4*>(&acc_s[warp][lane * 4])[0] = make_float4(a0, a1, a2, a3);
    __syncthreads();

    float* part = g_part + (((size_t)HOP * B_ + b) * SLICES + sl) * 132;
    if (tid < D_) {
        float o = 0.f;
        #pragma unroll
        for (int w = 0; w < 8; w++) o += acc_s[w][tid];
        part[tid] = o;
    } else if (tid == D_) {
        float lt = 0.f;
        #pragma unroll
        for (int w = 0; w < 8; w++) lt += lw_s[w];
        part[D_] = lt;
    }
}

extern "C" void kernel_launch(void* const* d_in, const int* in_sizes, int n_in,
                              void* d_out, int out_size)
{
    // 0 e1, 1 rel(unused), 2 key(unused), 3 value, 4 mask,
    // 5 linfc_w, 6 linfc_b, 7 attfc_w, 8 attfc_b, 9 dim(unused)
    const float* e1    = (const float*)d_in[0];
    const float* value = (const float*)d_in[3];
    const float* nmask = (const float*)d_in[4];
    const float* linw  = (const float*)d_in[5];
    const float* linb  = (const float*)d_in[6];
    const float* attw  = (const float*)d_in[7];
    const float* attb  = (const float*)d_in[8];
    (void)in_sizes; (void)n_in; (void)out_size;

    dmn_k1<<<B_ * SLICES, 256>>>(e1, value, nmask, attw, attb);
    dmn_hop<1><<<B_ * SLICES, 256>>>(e1, linw, linb, attw, attb, (float*)d_out);
    dmn_hop<2><<<B_ * SLICES, 256>>>(e1, linw, linb, attw, attb, (float*)d_out);
    dmn_hop<3><<<B_, 256>>>(e1, linw, linb, attw, attb, (float*)d_out);
}

// round 10
// speedup vs baseline: 1.4053x; 1.4053x over previous
#include <cuda_runtime.h>
#include <cuda_bf16.h>

// DMN_Encoder: 3-hop memory network, B=128, N=2048, D=128. Single kernel,
// CTA-per-batch (R3 shape), but hops 1 and 2 FUSED into one bf16 pass:
//  Pass A (fp32, active rows only): s[k]=v·w_f, t[k]=v·w_u (both exact),
//    bf16 compact scratch write, and full hop-0 accumulation (c0 from e1).
//  Scalar interlude: c1 from u1; c2 = ub(u1)·w_u + (Σ w1·t)/l1' + b0 — no
//    vector pass needed (t-based lookahead). Both weight vectors w1,w2 swept.
//  Pass B (bf16, once): accumulate o1 AND o2 simultaneously.
//  Tail: u2 = ub1 + o1/l1'; out = relu(u2 W^T+lb) + o2/l2'.

#define B_ 128
#define N_ 2048
#define D_ 128

__device__ uint2 g_vbf[(size_t)B_ * N_ * (D_ / 4)];   // 67MB compact bf16 scratch

__device__ __forceinline__ float wsum(float v) {
    #pragma unroll
    for (int o = 16; o; o >>= 1) v += __shfl_xor_sync(0xffffffffu, v, o);
    return v;
}

// ub[i] = relu(dot(linw[i,:], u) + linb[i]); warp w handles rows 4w..4w+3.
__device__ __forceinline__ void gemv_relu(const float4 u4,
                                          const float* __restrict__ linw,
                                          const float* __restrict__ linb,
                                          float* dst, int warp, int lane)
{
    #pragma unroll
    for (int r = 0; r < 4; r++) {
        const int i = warp * 4 + r;
        const float4 w4 = reinterpret_cast<const float4*>(linw + (size_t)i * D_)[lane];
        float p = w4.x*u4.x + w4.y*u4.y + w4.z*u4.z + w4.w*u4.w;
        p = wsum(p);
        if (lane == 0) dst[i] = fmaxf(p + linb[i], 0.f);
    }
}

__global__ __launch_bounds__(1024, 1)
void dmn_fused(const float* __restrict__ e1,
               const float* __restrict__ value,
               const float* __restrict__ mask,
               const float* __restrict__ linw,
               const float* __restrict__ linb,
               const float* __restrict__ attw,
               const float* __restrict__ attb,
               float* __restrict__ out)
{
    const int b    = blockIdx.x;
    const int tid  = threadIdx.x;
    const int lane = tid & 31;
    const int warp = tid >> 5;

    __shared__ float s_s[N_];                 // 8K  hop-invariant s (compact)
    __shared__ float w1_s[N_];                // 8K  (compaction staging, then w1)
    __shared__ float tw2_s[N_];               // 8K  t, then w2
    __shared__ unsigned short dense_s[N_];    // 4K
    __shared__ __align__(16) float u_s[D_], ub_s[D_], ub1_s[D_], u2_s[D_];
    __shared__ __align__(16) float acc8[8][D_];   // 4K phased accumulator
    __shared__ float red_s[4][32];            // l0, l1, st, l2 warp partials
    __shared__ int cnt_s[32], off_s[32], tot_s;

    const float4* attw4 = reinterpret_cast<const float4*>(attw);
    const float4 wf4 = attw4[lane];
    const float4 wu4 = attw4[32 + lane];
    const float  b0  = attb[0];

    const float* vb = value + (size_t)b * N_ * D_;
    const float* mb = mask  + (size_t)b * N_;

    if (tid < D_) u_s[tid] = e1[b * D_ + tid];

    // ---- ballot compaction of active rows (stage in w1_s bytes) ----
    {
        const int base = warp * 64;
        const float m0 = mb[base + lane];
        const float m1 = mb[base + 32 + lane];
        const unsigned bal0 = __ballot_sync(0xffffffffu, m0 != 0.f);
        const unsigned bal1 = __ballot_sync(0xffffffffu, m1 != 0.f);
        const int c0n = __popc(bal0);
        unsigned short* tmp = (unsigned short*)w1_s;
        if (m0 != 0.f)
            tmp[base + __popc(bal0 & ((1u << lane) - 1u))] = (unsigned short)(base + lane);
        if (m1 != 0.f)
            tmp[base + c0n + __popc(bal1 & ((1u << lane) - 1u))] = (unsigned short)(base + 32 + lane);
        if (lane == 0) cnt_s[warp] = c0n + __popc(bal1);
    }
    __syncthreads();
    if (warp == 0) {
        int c = cnt_s[lane], x = c;
        #pragma unroll
        for (int o = 1; o < 32; o <<= 1) {
            int y = __shfl_up_sync(0xffffffffu, x, o);
            if (lane >= o) x += y;
        }
        off_s[lane] = x - c;
        if (lane == 31) tot_s = x;
    }
    __syncthreads();
    {
        const unsigned short* tmp = (const unsigned short*)w1_s;
        const int off = off_s[warp], cc = cnt_s[warp];
        for (int j = lane; j < cc; j += 32)
            dense_s[off + j] = tmp[warp * 64 + j];
    }
    __syncthreads();

    const int cnt = tot_s;
    const int kb  = (cnt * warp) >> 5;
    const int ke  = (cnt * (warp + 1)) >> 5;

    // ---- c0 = e1·w_u + b0 ; ub0 = relu(e1 W^T + lb) ----
    const float4 u04 = reinterpret_cast<const float4*>(u_s)[lane];
    const float c0 = wsum(u04.x*wu4.x + u04.y*wu4.y + u04.z*wu4.z + u04.w*wu4.w) + b0;
    const float sg0 = fmaxf(c0, 0.f);
    gemv_relu(u04, linw, linb, ub_s, warp, lane);

    // ================= PASS A: fp32 stream (once) =================
    float a0 = 0.f, a1 = 0.f, a2 = 0.f, a3 = 0.f, l0 = 0.f;
    #pragma unroll 4
    for (int k = kb; k < ke; k++) {
        const int n = dense_s[k];
        const float4 v4 = reinterpret_cast<const float4*>(vb + (size_t)n * D_)[lane];
        const float s = wsum(v4.x*wf4.x + v4.y*wf4.y + v4.z*wf4.z + v4.w*wf4.w);
        const float t = wsum(v4.x*wu4.x + v4.y*wu4.y + v4.z*wu4.z + v4.w*wu4.w);
        if (lane == 0) { s_s[k] = s; tw2_s[k] = t; }
        __nv_bfloat162 p0 = __floats2bfloat162_rn(v4.x, v4.y);
        __nv_bfloat162 p1 = __floats2bfloat162_rn(v4.z, v4.w);
        uint2 pk;
        pk.x = *reinterpret_cast<unsigned int*>(&p0);
        pk.y = *reinterpret_cast<unsigned int*>(&p1);
        g_vbf[((size_t)b * N_ + k) * 32 + lane] = pk;
        const float w = __expf(fminf(fmaxf(s + c0, 0.f) - sg0, 80.f));
        l0 += w;
        a0 = fmaf(w, v4.x, a0);
        a1 = fmaf(w, v4.y, a1);
        a2 = fmaf(w, v4.z, a2);
        a3 = fmaf(w, v4.w, a3);
    }
    if (lane == 0) red_s[0][warp] = l0;   // l0 warp-uniform

    // phased accumulate o0 into acc8
    #pragma unroll 1
    for (int g = 0; g < 4; g++) {
        __syncthreads();
        if ((warp >> 3) == g) {
            float* dst = acc8[warp & 7] + lane * 4;
            if (g == 0) { dst[0] = a0; dst[1] = a1; dst[2] = a2; dst[3] = a3; }
            else        { dst[0] += a0; dst[1] += a1; dst[2] += a2; dst[3] += a3; }
        }
    }
    __syncthreads();

    // u1 = ub0 + o0/l0'
    if (tid < D_) {
        const float l0tot = wsum(red_s[0][lane]) + 1e-5f;
        float o = 0.f;
        #pragma unroll
        for (int j = 0; j < 8; j++) o += acc8[j][tid];
        u_s[tid] = ub_s[tid] + o / l0tot;
    }
    __syncthreads();

    // ---- c1 ; ub1 = relu(u1 W^T + lb) ----
    const float4 u14 = reinterpret_cast<const float4*>(u_s)[lane];
    const float c1 = wsum(u14.x*wu4.x + u14.y*wu4.y + u14.z*wu4.z + u14.w*wu4.w) + b0;
    const float sg1 = fmaxf(c1, 0.f);
    gemv_relu(u14, linw, linb, ub1_s, warp, lane);

    // ---- sweep 1: w1[k], l1, st = Σ w1·t ----
    {
        float l1p = 0.f, stp = 0.f;
        for (int k = tid; k < cnt; k += 1024) {
            const float w1 = __expf(fminf(fmaxf(s_s[k] + c1, 0.f) - sg1, 80.f));
            w1_s[k] = w1;
            l1p += w1;
            stp  = fmaf(w1, tw2_s[k], stp);
        }
        l1p = wsum(l1p); stp = wsum(stp);
        if (lane == 0) { red_s[1][warp] = l1p; red_s[2][warp] = stp; }
    }
    __syncthreads();

    // ---- scalar lookahead: c2 = ub1·w_u + st/l1' + b0 ----
    const float l1tot = wsum(red_s[1][lane]) + 1e-5f;
    const float sttot = wsum(red_s[2][lane]);
    const float4 b14 = reinterpret_cast<const float4*>(ub1_s)[lane];
    const float cu2b = wsum(b14.x*wu4.x + b14.y*wu4.y + b14.z*wu4.z + b14.w*wu4.w);
    const float c2  = cu2b + sttot / l1tot + b0;
    const float sg2 = fmaxf(c2, 0.f);

    // ---- sweep 2: w2[k] (overwrites t), l2 ----
    {
        float l2p = 0.f;
        for (int k = tid; k < cnt; k += 1024) {
            const float w2 = __expf(fminf(fmaxf(s_s[k] + c2, 0.f) - sg2, 80.f));
            tw2_s[k] = w2;
            l2p += w2;
        }
        l2p = wsum(l2p);
        if (lane == 0) red_s[3][warp] = l2p;
    }
    __syncthreads();

    // ================= PASS B: bf16 stream, o1 AND o2 =================
    float x0 = 0.f, x1 = 0.f, x2 = 0.f, x3 = 0.f;   // o1
    float y0 = 0.f, y1 = 0.f, y2 = 0.f, y3 = 0.f;   // o2
    const uint2* vbf = g_vbf + (size_t)b * N_ * 32;
    #pragma unroll 8
    for (int k = kb; k < ke; k++) {
        const uint2 pk = vbf[(size_t)k * 32 + lane];
        const float w1 = w1_s[k];
        const float w2 = tw2_s[k];
        const float2 f0 = __bfloat1622float2(*reinterpret_cast<const __nv_bfloat162*>(&pk.x));
        const float2 f1 = __bfloat1622float2(*reinterpret_cast<const __nv_bfloat162*>(&pk.y));
        x0 = fmaf(w1, f0.x, x0); x1 = fmaf(w1, f0.y, x1);
        x2 = fmaf(w1, f1.x, x2); x3 = fmaf(w1, f1.y, x3);
        y0 = fmaf(w2, f0.x, y0); y1 = fmaf(w2, f0.y, y1);
        y2 = fmaf(w2, f1.x, y2); y3 = fmaf(w2, f1.y, y3);
    }

    // reduce o1 -> u2
    #pragma unroll 1
    for (int g = 0; g < 4; g++) {
        __syncthreads();
        if ((warp >> 3) == g) {
            float* dst = acc8[warp & 7] + lane * 4;
            if (g == 0) { dst[0] = x0; dst[1] = x1; dst[2] = x2; dst[3] = x3; }
            else        { dst[0] += x0; dst[1] += x1; dst[2] += x2; dst[3] += x3; }
        }
    }
    __syncthreads();
    if (tid < D_) {
        float o = 0.f;
        #pragma unroll
        for (int j = 0; j < 8; j++) o += acc8[j][tid];
        u2_s[tid] = ub1_s[tid] + o / l1tot;
    }
    __syncthreads();

    // ub2 = relu(u2 W^T + lb)
    const float4 u24 = reinterpret_cast<const float4*>(u2_s)[lane];
    gemv_relu(u24, linw, linb, ub_s, warp, lane);

    // reduce o2 -> output
    #pragma unroll 1
    for (int g = 0; g < 4; g++) {
        __syncthreads();
        if ((warp >> 3) == g) {
            float* dst = acc8[warp & 7] + lane * 4;
            if (g == 0) { dst[0] = y0; dst[1] = y1; dst[2] = y2; dst[3] = y3; }
            else        { dst[0] += y0; dst[1] += y1; dst[2] += y2; dst[3] += y3; }
        }
    }
    __syncthreads();
    if (tid < D_) {
        const float l2tot = wsum(red_s[3][lane]) + 1e-5f;
        float o = 0.f;
        #pragma unroll
        for (int j = 0; j < 8; j++) o += acc8[j][tid];
        out[(size_t)b * D_ + tid] = ub_s[tid] + o / l2tot;
    }
}

extern "C" void kernel_launch(void* const* d_in, const int* in_sizes, int n_in,
                              void* d_out, int out_size)
{
    // 0 e1, 1 rel(unused), 2 key(unused), 3 value, 4 mask,
    // 5 linfc_w, 6 linfc_b, 7 attfc_w, 8 attfc_b, 9 dim(unused)
    const float* e1    = (const float*)d_in[0];
    const float* value = (const float*)d_in[3];
    const float* nmask = (const float*)d_in[4];
    const float* linw  = (const float*)d_in[5];
    const float* linb  = (const float*)d_in[6];
    const float* attw  = (const float*)d_in[7];
    const float* attb  = (const float*)d_in[8];
    (void)in_sizes; (void)n_in; (void)out_size;

    dmn_fused<<<B_, 1024>>>(e1, value, nmask, linw, linb, attw, attb,
                            (float*)d_out);
}